// round 16
// baseline (speedup 1.0000x reference)
#include <cuda_runtime.h>
#include <cstdint>
#include <math.h>

#define T_STEPS 512
#define BATCH   32
#define EMBED   512
#define HID     1024
#define G4      4096

#define NB  128
#define NT  512
#define WSS 1028            // W row stride (floats): rows 4 banks apart, 16B aligned
#define HQ4 33              // h-chunk row stride in float4
#define PRS 33              // partials row stride (floats)
#define PKS (32 * PRS)      // partials per k-slice

#define OFF_HN ((size_t)BATCH * T_STEPS * HID)
#define OFF_CN (OFF_HN + (size_t)BATCH * HID)

typedef unsigned long long u64;

__device__ float g_xproj[(size_t)T_STEPS * BATCH * G4]; // [t][b][j] (coalesced writes)
__device__ float g_h[2][BATCH * HID];                   // ping-pong h
__device__ unsigned g_count;                            // init barrier
__device__ volatile unsigned g_gen;
__device__ int g_gcnt[4 * 32];                          // group counters, 128B apart

__device__ __forceinline__ void ffma2(u64 &d, u64 a, u64 b) {
    asm("fma.rn.f32x2 %0, %1, %2, %0;" : "+l"(d) : "l"(a), "l"(b));
}
__device__ __forceinline__ u64 pk2(float x, float y) {
    u64 r; asm("mov.b64 %0, {%1, %2};" : "=l"(r) : "f"(x), "f"(y)); return r;
}
__device__ __forceinline__ float2 upk(u64 v) {
    float2 r; asm("mov.b64 {%0, %1}, %2;" : "=f"(r.x), "=f"(r.y) : "l"(v)); return r;
}
__device__ __forceinline__ int ld_acquire(const int* p) {
    int v; asm volatile("ld.acquire.gpu.global.b32 %0, [%1];" : "=r"(v) : "l"(p)); return v;
}
__device__ __forceinline__ void red_add_release(int* p, int v) {
    asm volatile("red.add.release.gpu.global.s32 [%0], %1;" :: "l"(p), "r"(v) : "memory");
}
__device__ __forceinline__ void wait_flag(const int* p, int need) {
    while (ld_acquire(p) < need) { }
}
// cp.async.cg: 16B global(L2)->shared, bypasses L1 (cross-SM coherent path)
__device__ __forceinline__ void cp_async16(void* smem_dst, const void* gsrc) {
    unsigned sa = (unsigned)__cvta_generic_to_shared(smem_dst);
    asm volatile("cp.async.cg.shared.global [%0], [%1], 16;" :: "r"(sa), "l"(gsrc) : "memory");
}
__device__ __forceinline__ void cp_async_commit() {
    asm volatile("cp.async.commit_group;" ::: "memory");
}
__device__ __forceinline__ void cp_async_wait_all() {
    asm volatile("cp.async.wait_group 0;" ::: "memory");
}

__device__ __forceinline__ void grid_barrier() {
    __syncthreads();
    if (threadIdx.x == 0) {
        unsigned gen = g_gen;
        __threadfence();
        unsigned prev = atomicAdd(&g_count, 1u);
        if (prev == NB - 1) {
            g_count = 0;
            __threadfence();
            g_gen = gen + 1;
        } else {
            while (g_gen == gen) { __nanosleep(32); }
        }
        __threadfence();
    }
    __syncthreads();
}

// ---------------------------------------------------------------------------
// Kernel 1: x_proj[t][b][j] = sum_e emb[ids[b][t]][e] * Wih[j][e]
// (R14 verbatim: R12 inner loop + [t][b][j] coalesced epilogue)
// ---------------------------------------------------------------------------
__global__ void __launch_bounds__(256, 2) xproj_gemm(
    const int* __restrict__ ids,
    const float* __restrict__ emb,
    const float* __restrict__ Wih)
{
    __shared__ float As[2][8][132];
    __shared__ float Bs[2][8][132];

    const int m0  = blockIdx.y * 128;
    const int n0  = blockIdx.x * 128;
    const int tid = threadIdx.x;

    const int mm = tid >> 1;
    const int qa = tid & 1;
    const int gm = m0 + mm;
    const int tt = gm >> 5;
    const int bb = gm & 31;
    const float* arow = emb + (size_t)ids[bb * T_STEPS + tt] * EMBED;
    const float* brow = Wih + (size_t)(n0 + mm) * EMBED;

    const int tm = tid >> 4;
    const int tn = tid & 15;

    u64 accp[8][4];
#pragma unroll
    for (int i = 0; i < 8; i++)
#pragma unroll
        for (int j = 0; j < 4; j++) accp[i][j] = 0ull;

    {
        float4 av = *(const float4*)(arow + qa * 4);
        float4 bv = *(const float4*)(brow + qa * 4);
        As[0][qa * 4 + 0][mm] = av.x; As[0][qa * 4 + 1][mm] = av.y;
        As[0][qa * 4 + 2][mm] = av.z; As[0][qa * 4 + 3][mm] = av.w;
        Bs[0][qa * 4 + 0][mm] = bv.x; Bs[0][qa * 4 + 1][mm] = bv.y;
        Bs[0][qa * 4 + 2][mm] = bv.z; Bs[0][qa * 4 + 3][mm] = bv.w;
    }
    __syncthreads();

    const int NTILE = EMBED / 8;   // 64
#pragma unroll 1
    for (int kt = 0; kt < NTILE; kt++) {
        const int buf = kt & 1;

        float4 av, bv;
        const bool more = (kt + 1) < NTILE;
        if (more) {
            av = *(const float4*)(arow + (kt + 1) * 8 + qa * 4);
            bv = *(const float4*)(brow + (kt + 1) * 8 + qa * 4);
        }

#pragma unroll
        for (int kk = 0; kk < 8; kk++) {
            float4 a0 = *(const float4*)(&As[buf][kk][tm * 8]);
            float4 a1 = *(const float4*)(&As[buf][kk][tm * 8 + 4]);
            const u64* bp = (const u64*)(&Bs[buf][kk][tn * 8]);
            u64 b0 = bp[0], b1 = bp[1], b2 = bp[2], b3 = bp[3];
            u64 ad[8];
            ad[0] = pk2(a0.x, a0.x); ad[1] = pk2(a0.y, a0.y);
            ad[2] = pk2(a0.z, a0.z); ad[3] = pk2(a0.w, a0.w);
            ad[4] = pk2(a1.x, a1.x); ad[5] = pk2(a1.y, a1.y);
            ad[6] = pk2(a1.z, a1.z); ad[7] = pk2(a1.w, a1.w);
#pragma unroll
            for (int i = 0; i < 8; i++) {
                ffma2(accp[i][0], ad[i], b0);
                ffma2(accp[i][1], ad[i], b1);
                ffma2(accp[i][2], ad[i], b2);
                ffma2(accp[i][3], ad[i], b3);
            }
        }

        if (more) {
            const int nb = buf ^ 1;
            As[nb][qa * 4 + 0][mm] = av.x; As[nb][qa * 4 + 1][mm] = av.y;
            As[nb][qa * 4 + 2][mm] = av.z; As[nb][qa * 4 + 3][mm] = av.w;
            Bs[nb][qa * 4 + 0][mm] = bv.x; Bs[nb][qa * 4 + 1][mm] = bv.y;
            Bs[nb][qa * 4 + 2][mm] = bv.z; Bs[nb][qa * 4 + 3][mm] = bv.w;
            __syncthreads();
        }
    }

#pragma unroll
    for (int i = 0; i < 8; i++) {
        const int gmi = m0 + tm * 8 + i;      // m row = t*32 + b
        float* base = g_xproj + (size_t)gmi * G4 + n0 + tn * 8;
#pragma unroll
        for (int jp = 0; jp < 4; jp++) {
            float2 v = upk(accp[i][jp]);
            *(float2*)(base + jp * 2) = v;
        }
    }
}

// ---------------------------------------------------------------------------
// Kernel 2: persistent LSTM, 512 threads. R14 compute core + dataflow group
// sync; h staging switched from LDG+STS to cp.async.cg (L2->smem direct:
// no STS wavefronts, no staging registers). Issue of chunk i+1 happens AFTER
// sync(i), so buf[(i+1)&1]'s prior readers (compute i-1, finished before
// sync(i)) are done — same two-sync WAR invariant as R14.
// ---------------------------------------------------------------------------
__global__ void __launch_bounds__(NT, 1) lstm_seq(
    const float* __restrict__ h0,
    const float* __restrict__ c0,
    const float* __restrict__ Whh,
    float* __restrict__ out)
{
    extern __shared__ float sm[];
    float*  Ws   = sm;                        // 32*1028 floats = 131,584 B
    float4* hq4  = (float4*)(sm + 32 * WSS);  // 2 * 64*33 float4 = 67,584 B
    float*  part = (float*)hq4;               // overlay buffer 0

    const int tid = threadIdx.x;
    const int bid = blockIdx.x;
    const int grp = bid >> 5;       // producer group 0..3
    const int n0  = bid * 8;

    if (tid == 0 && bid < 4) g_gcnt[bid * 32] = 0;

    {
        const int rr = tid >> 4, seg = tid & 15;
        const int grow = (rr >> 3) * HID + n0 + (rr & 7);
        const float4* src = (const float4*)(Whh + (size_t)grow * HID);
        float4* dst = (float4*)(Ws + rr * WSS);
#pragma unroll
        for (int q = 0; q < 16; q++) dst[seg + 16 * q] = src[seg + 16 * q];
    }
    if (tid < 256) {
        const int b = tid >> 3, i = tid & 7;
        g_h[0][b * HID + n0 + i] = h0[b * HID + n0 + i];
    }

    const int wid  = tid >> 5, lane = tid & 31;
    const int ks   = wid & 7;
    const int bh   = wid >> 3;
    const int rg   = lane >> 2;
    const int bg   = lane & 3;
    const int b0   = bh * 16 + bg;
    const int sb   = tid >> 4, ss = tid & 15;
    const int fi   = (tid >> 5) & 7, fb = tid & 31;
    const int cidx = fb * HID + n0 + fi;
    float c_reg = (tid < 256) ? c0[cidx] : 0.f;
    float h_reg = 0.f;

    const float* wr0 = Ws + (0 * 8 + rg) * WSS + ks * 4;
    const float* wr1 = Ws + (1 * 8 + rg) * WSS + ks * 4;
    const float* wr2 = Ws + (2 * 8 + rg) * WSS + ks * 4;
    const float* wr3 = Ws + (3 * 8 + rg) * WSS + ks * 4;

    grid_barrier();

    for (int t = 0; t < T_STEPS; t++) {
        const float* hread = g_h[t & 1];
        float* hwrite      = g_h[(t & 1) ^ 1];
        const int need = 32 * t;

        // x_proj gate loads, [t][b][j] layout
        float xg0 = 0.f, xg1 = 0.f, xg2 = 0.f, xg3 = 0.f;
        if (tid < 256) {
            const float* xpt = g_xproj + ((size_t)t * BATCH + fb) * G4 + n0 + fi;
            xg0 = xpt[0 * HID];
            xg1 = xpt[1 * HID];
            xg2 = xpt[2 * HID];
            xg3 = xpt[3 * HID];
        }

        u64 acc[4][4];
#pragma unroll
        for (int g = 0; g < 4; g++)
#pragma unroll
            for (int j = 0; j < 4; j++) acc[g][j] = 0ull;

        const float4* gsrc = (const float4*)(hread + sb * HID);

        // preamble: wait own-cohort flag, async-copy chunk 0 into buffer 0
        {
            if (need > 0) wait_flag(&g_gcnt[grp * 32], need);
            float4* buf = hq4;
#pragma unroll
            for (int q = 0; q < 4; q++)
                cp_async16(&buf[(ss + 16 * q) * HQ4 + sb],
                           gsrc + grp * 64 + ss + 16 * q);
            cp_async_commit();
        }

#pragma unroll 1
        for (int i = 0; i < 4; i++) {
            const int lc = (grp + i) & 3;
            float4* buf = hq4 + (i & 1) * (64 * HQ4);

            cp_async_wait_all();   // chunk i landed in buf
            __syncthreads();       // visible to all; compute(i-1) readers done

            // async-copy chunk i+1 into the other buffer (overlaps compute i)
            if (i < 3) {
                const int lcn = (grp + i + 1) & 3;
                if (need > 0) wait_flag(&g_gcnt[lcn * 32], need);
                float4* nbuf = hq4 + ((i + 1) & 1) * (64 * HQ4);
#pragma unroll
                for (int q = 0; q < 4; q++)
                    cp_async16(&nbuf[(ss + 16 * q) * HQ4 + sb],
                               gsrc + lcn * 64 + ss + 16 * q);
                cp_async_commit();
            }

            const float4* hb = buf + ks * HQ4 + b0;
            const float* wc0 = wr0 + lc * 256;
            const float* wc1 = wr1 + lc * 256;
            const float* wc2 = wr2 + lc * 256;
            const float* wc3 = wr3 + lc * 256;
#pragma unroll
            for (int m = 0; m < 8; m++) {
                float4 hv[4];
#pragma unroll
                for (int j = 0; j < 4; j++)
                    hv[j] = hb[m * 8 * HQ4 + 4 * j];
                float4 wv[4];
                wv[0] = *(const float4*)(wc0 + m * 32);
                wv[1] = *(const float4*)(wc1 + m * 32);
                wv[2] = *(const float4*)(wc2 + m * 32);
                wv[3] = *(const float4*)(wc3 + m * 32);
#pragma unroll
                for (int g = 0; g < 4; g++) {
                    const u64* wp = (const u64*)&wv[g];
#pragma unroll
                    for (int j = 0; j < 4; j++) {
                        const u64* hp = (const u64*)&hv[j];
                        ffma2(acc[g][j], wp[0], hp[0]);
                        ffma2(acc[g][j], wp[1], hp[1]);
                    }
                }
            }
        }

        // fold k-pairs, write partials: part[ks][r][(b+r)&31] (rotated cols).
        // Overlay on buffer 0 is safe: compute(2) readers of buffer 0 all
        // passed sync(3); chunk-3 compute reads buffer 1 only.
#pragma unroll
        for (int g = 0; g < 4; g++)
#pragma unroll
            for (int j = 0; j < 4; j++) {
                float2 v = upk(acc[g][j]);
                const int r = rg + 8 * g;
                const int b = b0 + 4 * j;
                part[ks * PKS + r * PRS + ((b + r) & 31)] = v.x + v.y;
            }
        __syncthreads();

        // gate fusion + state update (thread owns (n0+fi, fb))
        if (tid < 256) {
            float g[4] = {xg0, xg1, xg2, xg3};
#pragma unroll
            for (int gg = 0; gg < 4; gg++) {
                const int r = gg * 8 + fi;
                const int col = (fb + r) & 31;
#pragma unroll
                for (int kx = 0; kx < 8; kx++)
                    g[gg] += part[kx * PKS + r * PRS + col];
            }
            const float I = 1.f / (1.f + expf(-g[0]));
            const float F = 1.f / (1.f + expf(-g[1]));
            const float G = tanhf(g[2]);
            const float O = 1.f / (1.f + expf(-g[3]));
            c_reg = F * c_reg + I * G;
            h_reg = O * tanhf(c_reg);

            hwrite[cidx] = h_reg;
            out[((size_t)fb * T_STEPS + t) * HID + n0 + fi] = h_reg;
        }

        // publish: h stores done -> release-add to own group's counter
        __syncthreads();
        if (tid == 0) red_add_release(&g_gcnt[grp * 32], 1);
    }

    if (tid < 256) {
        out[OFF_HN + cidx] = h_reg;
        out[OFF_CN + cidx] = c_reg;
    }
}

// ---------------------------------------------------------------------------
extern "C" void kernel_launch(void* const* d_in, const int* in_sizes, int n_in,
                              void* d_out, int out_size)
{
    (void)in_sizes; (void)n_in; (void)out_size;
    const int*   ids = (const int*)  d_in[0];
    const float* h0  = (const float*)d_in[1];
    const float* c0  = (const float*)d_in[2];
    const float* emb = (const float*)d_in[3];
    const float* Wih = (const float*)d_in[4];
    const float* Whh = (const float*)d_in[5];
    float* out = (float*)d_out;

    const int smem_bytes = 32 * WSS * 4 + 2 * 64 * HQ4 * 16; // 199,168 B
    cudaFuncSetAttribute(lstm_seq, cudaFuncAttributeMaxDynamicSharedMemorySize, smem_bytes);

    dim3 ggrid(G4 / 128, (BATCH * T_STEPS) / 128);
    xproj_gemm<<<ggrid, 256>>>(ids, emb, Wih);
    lstm_seq<<<NB, NT, smem_bytes>>>(h0, c0, Whh, out);
}

// round 17
// speedup vs baseline: 1.3797x; 1.3797x over previous
#include <cuda_runtime.h>
#include <cstdint>
#include <math.h>

#define T_STEPS 512
#define BATCH   32
#define EMBED   512
#define HID     1024
#define G4      4096

#define NB  512
#undef NB
#define NB  128
#define NT  512
#define WSS 1028            // W row stride (floats): rows 4 banks apart, 16B aligned
#define HQ4 33              // h-chunk row stride in float4
#define PRS 33              // partials row stride (floats)
#define PKS (32 * PRS)      // partials per k-slice

#define OFF_HN ((size_t)BATCH * T_STEPS * HID)
#define OFF_CN (OFF_HN + (size_t)BATCH * HID)

typedef unsigned long long u64;

__device__ float g_xproj[(size_t)T_STEPS * BATCH * G4]; // [t][b][j] (coalesced writes)
__device__ float g_h[2][BATCH * HID];                   // ping-pong h
__device__ unsigned g_count;                            // init barrier
__device__ volatile unsigned g_gen;
__device__ int g_gcnt[4 * 32];                          // group counters, 128B apart

__device__ __forceinline__ void ffma2(u64 &d, u64 a, u64 b) {
    asm("fma.rn.f32x2 %0, %1, %2, %0;" : "+l"(d) : "l"(a), "l"(b));
}
__device__ __forceinline__ u64 pk2(float x, float y) {
    u64 r; asm("mov.b64 %0, {%1, %2};" : "=l"(r) : "f"(x), "f"(y)); return r;
}
__device__ __forceinline__ float2 upk(u64 v) {
    float2 r; asm("mov.b64 {%0, %1}, %2;" : "=f"(r.x), "=f"(r.y) : "l"(v)); return r;
}
__device__ __forceinline__ int ld_acquire(const int* p) {
    int v; asm volatile("ld.acquire.gpu.global.b32 %0, [%1];" : "=r"(v) : "l"(p)); return v;
}
__device__ __forceinline__ void red_add_release(int* p, int v) {
    asm volatile("red.add.release.gpu.global.s32 [%0], %1;" :: "l"(p), "r"(v) : "memory");
}
__device__ __forceinline__ void wait_flag(const int* p, int need) {
    while (ld_acquire(p) < need) { }
}

__device__ __forceinline__ void grid_barrier() {
    __syncthreads();
    if (threadIdx.x == 0) {
        unsigned gen = g_gen;
        __threadfence();
        unsigned prev = atomicAdd(&g_count, 1u);
        if (prev == NB - 1) {
            g_count = 0;
            __threadfence();
            g_gen = gen + 1;
        } else {
            while (g_gen == gen) { __nanosleep(32); }
        }
        __threadfence();
    }
    __syncthreads();
}

// ---------------------------------------------------------------------------
// Kernel 1: x_proj[t][b][j] = sum_e emb[ids[b][t]][e] * Wih[j][e]
// (R14 verbatim: R12 inner loop + [t][b][j] coalesced epilogue)
// ---------------------------------------------------------------------------
__global__ void __launch_bounds__(256, 2) xproj_gemm(
    const int* __restrict__ ids,
    const float* __restrict__ emb,
    const float* __restrict__ Wih)
{
    __shared__ float As[2][8][132];
    __shared__ float Bs[2][8][132];

    const int m0  = blockIdx.y * 128;
    const int n0  = blockIdx.x * 128;
    const int tid = threadIdx.x;

    const int mm = tid >> 1;
    const int qa = tid & 1;
    const int gm = m0 + mm;
    const int tt = gm >> 5;
    const int bb = gm & 31;
    const float* arow = emb + (size_t)ids[bb * T_STEPS + tt] * EMBED;
    const float* brow = Wih + (size_t)(n0 + mm) * EMBED;

    const int tm = tid >> 4;
    const int tn = tid & 15;

    u64 accp[8][4];
#pragma unroll
    for (int i = 0; i < 8; i++)
#pragma unroll
        for (int j = 0; j < 4; j++) accp[i][j] = 0ull;

    {
        float4 av = *(const float4*)(arow + qa * 4);
        float4 bv = *(const float4*)(brow + qa * 4);
        As[0][qa * 4 + 0][mm] = av.x; As[0][qa * 4 + 1][mm] = av.y;
        As[0][qa * 4 + 2][mm] = av.z; As[0][qa * 4 + 3][mm] = av.w;
        Bs[0][qa * 4 + 0][mm] = bv.x; Bs[0][qa * 4 + 1][mm] = bv.y;
        Bs[0][qa * 4 + 2][mm] = bv.z; Bs[0][qa * 4 + 3][mm] = bv.w;
    }
    __syncthreads();

    const int NTILE = EMBED / 8;   // 64
#pragma unroll 1
    for (int kt = 0; kt < NTILE; kt++) {
        const int buf = kt & 1;

        float4 av, bv;
        const bool more = (kt + 1) < NTILE;
        if (more) {
            av = *(const float4*)(arow + (kt + 1) * 8 + qa * 4);
            bv = *(const float4*)(brow + (kt + 1) * 8 + qa * 4);
        }

#pragma unroll
        for (int kk = 0; kk < 8; kk++) {
            float4 a0 = *(const float4*)(&As[buf][kk][tm * 8]);
            float4 a1 = *(const float4*)(&As[buf][kk][tm * 8 + 4]);
            const u64* bp = (const u64*)(&Bs[buf][kk][tn * 8]);
            u64 b0 = bp[0], b1 = bp[1], b2 = bp[2], b3 = bp[3];
            u64 ad[8];
            ad[0] = pk2(a0.x, a0.x); ad[1] = pk2(a0.y, a0.y);
            ad[2] = pk2(a0.z, a0.z); ad[3] = pk2(a0.w, a0.w);
            ad[4] = pk2(a1.x, a1.x); ad[5] = pk2(a1.y, a1.y);
            ad[6] = pk2(a1.z, a1.z); ad[7] = pk2(a1.w, a1.w);
#pragma unroll
            for (int i = 0; i < 8; i++) {
                ffma2(accp[i][0], ad[i], b0);
                ffma2(accp[i][1], ad[i], b1);
                ffma2(accp[i][2], ad[i], b2);
                ffma2(accp[i][3], ad[i], b3);
            }
        }

        if (more) {
            const int nb = buf ^ 1;
            As[nb][qa * 4 + 0][mm] = av.x; As[nb][qa * 4 + 1][mm] = av.y;
            As[nb][qa * 4 + 2][mm] = av.z; As[nb][qa * 4 + 3][mm] = av.w;
            Bs[nb][qa * 4 + 0][mm] = bv.x; Bs[nb][qa * 4 + 1][mm] = bv.y;
            Bs[nb][qa * 4 + 2][mm] = bv.z; Bs[nb][qa * 4 + 3][mm] = bv.w;
            __syncthreads();
        }
    }

#pragma unroll
    for (int i = 0; i < 8; i++) {
        const int gmi = m0 + tm * 8 + i;      // m row = t*32 + b
        float* base = g_xproj + (size_t)gmi * G4 + n0 + tn * 8;
#pragma unroll
        for (int jp = 0; jp < 4; jp++) {
            float2 v = upk(accp[i][jp]);
            *(float2*)(base + jp * 2) = v;
        }
    }
}

// ---------------------------------------------------------------------------
// Kernel 2: persistent LSTM, 512 threads. R14 compute core + dataflow group
// sync. Epilogue role REMAPPED: fe = tid&7 (n-index), be = tid>>3 (batch) —
// within a warp, 4 batches x 8 contiguous n-values, so xg loads / c0 load /
// out + hwrite stores hit 4x32B segments per warp instead of 32 scattered
// 4B accesses (8x fewer sectors on both L1 and DRAM paths).
// ---------------------------------------------------------------------------
__global__ void __launch_bounds__(NT, 1) lstm_seq(
    const float* __restrict__ h0,
    const float* __restrict__ c0,
    const float* __restrict__ Whh,
    float* __restrict__ out)
{
    extern __shared__ float sm[];
    float*  Ws   = sm;                        // 32*1028 floats = 131,584 B
    float4* hq4  = (float4*)(sm + 32 * WSS);  // 2 * 64*33 float4 = 67,584 B
    float*  part = (float*)hq4;               // overlay buffer 0

    const int tid = threadIdx.x;
    const int bid = blockIdx.x;
    const int grp = bid >> 5;       // producer group 0..3
    const int n0  = bid * 8;

    if (tid == 0 && bid < 4) g_gcnt[bid * 32] = 0;

    {
        const int rr = tid >> 4, seg = tid & 15;
        const int grow = (rr >> 3) * HID + n0 + (rr & 7);
        const float4* src = (const float4*)(Whh + (size_t)grow * HID);
        float4* dst = (float4*)(Ws + rr * WSS);
#pragma unroll
        for (int q = 0; q < 16; q++) dst[seg + 16 * q] = src[seg + 16 * q];
    }
    if (tid < 256) {
        const int b = tid >> 3, i = tid & 7;
        g_h[0][b * HID + n0 + i] = h0[b * HID + n0 + i];
    }

    const int wid  = tid >> 5, lane = tid & 31;
    const int ks   = wid & 7;
    const int bh   = wid >> 3;
    const int rg   = lane >> 2;
    const int bg   = lane & 3;
    const int b0   = bh * 16 + bg;
    const int sb   = tid >> 4, ss = tid & 15;
    // finalize role (tid<256): fe = n-index, be = batch (coalesced epilogue)
    const int fe   = tid & 7, be = (tid >> 3) & 31;
    const int cidx = be * HID + n0 + fe;
    float c_reg = (tid < 256) ? c0[cidx] : 0.f;
    float h_reg = 0.f;

    const float* wr0 = Ws + (0 * 8 + rg) * WSS + ks * 4;
    const float* wr1 = Ws + (1 * 8 + rg) * WSS + ks * 4;
    const float* wr2 = Ws + (2 * 8 + rg) * WSS + ks * 4;
    const float* wr3 = Ws + (3 * 8 + rg) * WSS + ks * 4;

    grid_barrier();

    for (int t = 0; t < T_STEPS; t++) {
        const float* hread = g_h[t & 1];
        float* hwrite      = g_h[(t & 1) ^ 1];
        const int need = 32 * t;

        // x_proj gate loads, [t][b][j] layout (4x32B segments per warp)
        float xg0 = 0.f, xg1 = 0.f, xg2 = 0.f, xg3 = 0.f;
        if (tid < 256) {
            const float* xpt = g_xproj + ((size_t)t * BATCH + be) * G4 + n0 + fe;
            xg0 = xpt[0 * HID];
            xg1 = xpt[1 * HID];
            xg2 = xpt[2 * HID];
            xg3 = xpt[3 * HID];
        }

        u64 acc[4][4];
#pragma unroll
        for (int g = 0; g < 4; g++)
#pragma unroll
            for (int j = 0; j < 4; j++) acc[g][j] = 0ull;

        const float4* gsrc = (const float4*)(hread + sb * HID);
        float4 sreg[4];

        {
            const int lc0 = grp;
            if (need > 0) wait_flag(&g_gcnt[lc0 * 32], need);
#pragma unroll
            for (int i = 0; i < 4; i++)
                sreg[i] = __ldcg(gsrc + lc0 * 64 + ss + 16 * i);
        }

#pragma unroll 1
        for (int i = 0; i < 4; i++) {
            const int lc = (grp + i) & 3;
            float4* buf = hq4 + (i & 1) * (64 * HQ4);
#pragma unroll
            for (int q = 0; q < 4; q++)
                buf[(ss + 16 * q) * HQ4 + sb] = sreg[q];
            if (i < 3) {
                const int lcn = (grp + i + 1) & 3;
                if (need > 0) wait_flag(&g_gcnt[lcn * 32], need);
#pragma unroll
                for (int q = 0; q < 4; q++)
                    sreg[q] = __ldcg(gsrc + lcn * 64 + ss + 16 * q);
            }
            __syncthreads();

            const float4* hb = buf + ks * HQ4 + b0;
            const float* wc0 = wr0 + lc * 256;
            const float* wc1 = wr1 + lc * 256;
            const float* wc2 = wr2 + lc * 256;
            const float* wc3 = wr3 + lc * 256;
#pragma unroll
            for (int m = 0; m < 8; m++) {
                float4 hv[4];
#pragma unroll
                for (int j = 0; j < 4; j++)
                    hv[j] = hb[m * 8 * HQ4 + 4 * j];
                float4 wv[4];
                wv[0] = *(const float4*)(wc0 + m * 32);
                wv[1] = *(const float4*)(wc1 + m * 32);
                wv[2] = *(const float4*)(wc2 + m * 32);
                wv[3] = *(const float4*)(wc3 + m * 32);
#pragma unroll
                for (int g = 0; g < 4; g++) {
                    const u64* wp = (const u64*)&wv[g];
#pragma unroll
                    for (int j = 0; j < 4; j++) {
                        const u64* hp = (const u64*)&hv[j];
                        ffma2(acc[g][j], wp[0], hp[0]);
                        ffma2(acc[g][j], wp[1], hp[1]);
                    }
                }
            }
        }

        // fold k-pairs, write partials: part[ks][r][(b+r)&31] (rotated cols)
#pragma unroll
        for (int g = 0; g < 4; g++)
#pragma unroll
            for (int j = 0; j < 4; j++) {
                float2 v = upk(acc[g][j]);
                const int r = rg + 8 * g;
                const int b = b0 + 4 * j;
                part[ks * PKS + r * PRS + ((b + r) & 31)] = v.x + v.y;
            }
        __syncthreads();

        // gate fusion + state update (thread owns (n0+fe, be))
        if (tid < 256) {
            float g[4] = {xg0, xg1, xg2, xg3};
#pragma unroll
            for (int gg = 0; gg < 4; gg++) {
                const int r = gg * 8 + fe;
                const int col = (be + r) & 31;
#pragma unroll
                for (int kx = 0; kx < 8; kx++)
                    g[gg] += part[kx * PKS + r * PRS + col];
            }
            const float I = 1.f / (1.f + expf(-g[0]));
            const float F = 1.f / (1.f + expf(-g[1]));
            const float G = tanhf(g[2]);
            const float O = 1.f / (1.f + expf(-g[3]));
            c_reg = F * c_reg + I * G;
            h_reg = O * tanhf(c_reg);

            hwrite[cidx] = h_reg;
            out[((size_t)be * T_STEPS + t) * HID + n0 + fe] = h_reg;
        }

        // publish: h stores done -> release-add to own group's counter
        __syncthreads();
        if (tid == 0) red_add_release(&g_gcnt[grp * 32], 1);
    }

    if (tid < 256) {
        out[OFF_HN + cidx] = h_reg;
        out[OFF_CN + cidx] = c_reg;
    }
}

// ---------------------------------------------------------------------------
extern "C" void kernel_launch(void* const* d_in, const int* in_sizes, int n_in,
                              void* d_out, int out_size)
{
    (void)in_sizes; (void)n_in; (void)out_size;
    const int*   ids = (const int*)  d_in[0];
    const float* h0  = (const float*)d_in[1];
    const float* c0  = (const float*)d_in[2];
    const float* emb = (const float*)d_in[3];
    const float* Wih = (const float*)d_in[4];
    const float* Whh = (const float*)d_in[5];
    float* out = (float*)d_out;

    const int smem_bytes = 32 * WSS * 4 + 2 * 64 * HQ4 * 16; // 199,168 B
    cudaFuncSetAttribute(lstm_seq, cudaFuncAttributeMaxDynamicSharedMemorySize, smem_bytes);

    dim3 ggrid(G4 / 128, (BATCH * T_STEPS) / 128);
    xproj_gemm<<<ggrid, 256>>>(ids, emb, Wih);
    lstm_seq<<<NB, NT, smem_bytes>>>(h0, c0, Whh, out);
}